// round 16
// baseline (speedup 1.0000x reference)
#include <cuda_runtime.h>
#include <cuda_bf16.h>
#include <math.h>
#include <stdint.h>

#define B_  256
#define T_  512
#define D_  128
#define H_  256
#define G_  768
#define C_  10

// ---------------- warp-mma helpers (sm_80+ baseline; compiles for plain sm_103) ---
__device__ __forceinline__ uint32_t smem_u32(const void* p) {
    uint32_t a;
    asm("{ .reg .u64 t; cvta.to.shared.u64 t, %1; cvt.u32.u64 %0, t; }" : "=r"(a) : "l"(p));
    return a;
}
#define LDSM4(r0, r1, r2, r3, addr) \
    asm volatile("ldmatrix.sync.aligned.m8n8.x4.shared.b16 {%0,%1,%2,%3}, [%4];" \
        : "=r"(r0), "=r"(r1), "=r"(r2), "=r"(r3) : "r"(addr))
#define MMA16816(c, a, b0v, b1v) \
    asm volatile("mma.sync.aligned.m16n8k16.row.col.f32.bf16.bf16.f32 " \
        "{%0,%1,%2,%3},{%4,%5,%6,%7},{%8,%9},{%0,%1,%2,%3};" \
        : "+f"((c)[0]), "+f"((c)[1]), "+f"((c)[2]), "+f"((c)[3]) \
        : "r"((a)[0]), "r"((a)[1]), "r"((a)[2]), "r"((a)[3]), "r"(b0v), "r"(b1v))

// ---------------- scratch (device globals; no allocation allowed) ----------------
__device__ __nv_bfloat16 g_seqhi[(size_t)T_ * B_ * H_]; // layer-0 h sequence, bf16 hi
__device__ __nv_bfloat16 g_seqlo[(size_t)T_ * B_ * H_]; // layer-0 h sequence, bf16 lo
__device__ __nv_bfloat16 g_hbhi[2][B_ * H_];            // layer-1 h ping-pong (hi)
__device__ __nv_bfloat16 g_hblo[2][B_ * H_];            // layer-1 h ping-pong (lo)
__device__ float g_hlast[B_ * H_];                      // final fp32 h2 for the FC
__device__ volatile unsigned g_gen0[4 * 32];            // layer-0 group generation
__device__ unsigned g_cnt0[4 * 32];
__device__ volatile unsigned g_gen1[4 * 32];            // layer-1 group generation
__device__ unsigned g_cnt1[4 * 32];
__device__ __nv_bfloat16 g_xhi[(size_t)B_ * T_ * D_];   // x split, bf16 hi
__device__ __nv_bfloat16 g_xlo[(size_t)B_ * T_ * D_];   // x split, bf16 lo

// ---------------- fp32 -> (bf16 hi, bf16 lo) split + barrier reset (fused) ---------
__global__ void split_bf16(const float* __restrict__ s, __nv_bfloat16* __restrict__ hi,
                           __nv_bfloat16* __restrict__ lo, int n4)
{
    // graph-replay-safe barrier reset, fused here to save a launch
    if (blockIdx.x == 0 && threadIdx.x < 128) {
        const int i = threadIdx.x;
        g_cnt0[i] = 0u; ((unsigned*)g_gen0)[i] = 0u;
        g_cnt1[i] = 0u; ((unsigned*)g_gen1)[i] = 0u;
    }
    const int i = blockIdx.x * blockDim.x + threadIdx.x;
    if (i >= n4) return;
    const float4 v = ((const float4*)s)[i];
    __nv_bfloat16 h0 = __float2bfloat16(v.x);
    __nv_bfloat16 h1 = __float2bfloat16(v.y);
    __nv_bfloat16 h2 = __float2bfloat16(v.z);
    __nv_bfloat16 h3 = __float2bfloat16(v.w);
    __nv_bfloat16 l0 = __float2bfloat16(v.x - __bfloat162float(h0));
    __nv_bfloat16 l1 = __float2bfloat16(v.y - __bfloat162float(h1));
    __nv_bfloat16 l2 = __float2bfloat16(v.z - __bfloat162float(h2));
    __nv_bfloat16 l3 = __float2bfloat16(v.w - __bfloat162float(h3));
    __nv_bfloat162* hp = (__nv_bfloat162*)hi;
    __nv_bfloat162* lp = (__nv_bfloat162*)lo;
    hp[i * 2 + 0] = __nv_bfloat162(h0, h1);
    hp[i * 2 + 1] = __nv_bfloat162(h2, h3);
    lp[i * 2 + 0] = __nv_bfloat162(l0, l1);
    lp[i * 2 + 1] = __nv_bfloat162(l2, l3);
}

// ---------------- fully fused two-layer GRU (R15 + staging reg-batches) ------------
// 128 CTAs x 256 threads. CTA<64: layer 0; CTA>=64: layer 1 (lags one step).
__global__ void __launch_bounds__(256, 1) gru_fused2(
    const float* __restrict__ Wih0, const float* __restrict__ bih0,
    const float* __restrict__ Whh0, const float* __restrict__ bhh0,
    const float* __restrict__ Wih1, const float* __restrict__ bih1,
    const float* __restrict__ Whh1, const float* __restrict__ bhh1)
{
    extern __shared__ char smc[];
    __nv_bfloat16* sih_h = (__nv_bfloat16*)smc;
    __nv_bfloat16* sih_l = (__nv_bfloat16*)(smc + 25344);
    __nv_bfloat16* shh_h = (__nv_bfloat16*)(smc + 50688);
    __nv_bfloat16* shh_l = (__nv_bfloat16*)(smc + 76032);
    char* sthi = smc + 101376;
    char* stlo = smc + 135168;
    float* part  = (float*)(smc + 168960);
    float* partN = (float*)(smc + 194048);
    float* hst   = (float*)(smc + 202752);
    float* bih   = (float*)(smc + 207104);
    float* bhh   = (float*)(smc + 207296);

    const int tid = threadIdx.x;
    const int cta = blockIdx.x;
    const int layer = cta >> 6;
    const int lid = cta & 63;
    const int bblk = lid >> 4, jblk = lid & 15;
    const int b0 = bblk * 64, j0 = jblk * 16;
    const int slot = bblk * 32;

    const float* WA = layer ? Wih1 : Wih0;
    const float* WB = layer ? Whh1 : Whh0;
    const float* bA = layer ? bih1 : bih0;
    const float* bB = layer ? bhh1 : bhh0;
    const int KA = layer ? 256 : 128;          // phase-A K
    const int nksA = layer ? 8 : 4;
    volatile unsigned* genp = layer ? g_gen1 : g_gen0;
    unsigned* cntp = layer ? g_cnt1 : g_cnt0;

    // ---- load + split weight slices (48 gate rows each) ----
    for (int idx = tid; idx < 48 * KA; idx += 256) {
        const int row = idx / KA, k = idx % KA;
        const float v = WA[(size_t)((row >> 4) * H_ + j0 + (row & 15)) * KA + k];
        const __nv_bfloat16 hi = __float2bfloat16(v);
        sih_h[row * 264 + k] = hi;
        sih_l[row * 264 + k] = __float2bfloat16(v - __bfloat162float(hi));
    }
    for (int idx = tid; idx < 48 * 256; idx += 256) {
        const int row = idx >> 8, k = idx & 255;
        const float v = WB[(size_t)((row >> 4) * H_ + j0 + (row & 15)) * H_ + k];
        const __nv_bfloat16 hi = __float2bfloat16(v);
        shh_h[row * 264 + k] = hi;
        shh_l[row * 264 + k] = __float2bfloat16(v - __bfloat162float(hi));
    }
    if (tid < 48) {
        bih[tid] = bA[(tid >> 4) * H_ + j0 + (tid & 15)];
        bhh[tid] = bB[(tid >> 4) * H_ + j0 + (tid & 15)];
    }
    for (int idx = tid; idx < 64 * 17; idx += 256) hst[idx] = 0.f;

    const int w = tid >> 5, lane = tid & 31;
    const int mt = w & 3, kh = w >> 2;
    const int aoff = (mt * 16 + (lane & 15)) * 528 + (lane >> 4) * 16;
    const int brow = (lane & 7) + ((lane >> 4) << 3);
    const int bko  = ((lane >> 3) & 1) * 16;
    const uint32_t uSth = smem_u32(sthi), uStl = smem_u32(stlo);
    const uint32_t uIhi = smem_u32(smc), uIlo = smem_u32(smc + 25344);
    const uint32_t uHhi = smem_u32(smc + 50688), uHlo = smem_u32(smc + 76032);
    __syncthreads();

    for (int t = 0; t < T_; t++) {
        const int cur = t & 1, nxt = cur ^ 1;

        // layer-1 waits for layer-0 to have produced h1(t)
        if (layer == 1) {
            if (tid == 0) {
                while (g_gen0[slot] < (unsigned)(t + 1)) {}
                __threadfence();
            }
            __syncthreads();
        }

        // ---- prefetch phase-B staging into registers (covered by phase A) ----
        uint4 pfh[8], pfl[8];
        if (t == 0) {
            const uint4 z4 = make_uint4(0u, 0u, 0u, 0u);
#pragma unroll
            for (int q = 0; q < 8; q++) { pfh[q] = z4; pfl[q] = z4; }
        } else if (layer == 0) {
#pragma unroll
            for (int q = 0; q < 8; q++) {
                const int v = tid + 256 * q;
                const int b = v >> 5, c = v & 31;
                const size_t so = ((size_t)(t - 1) * B_ + b0 + b) * H_ + c * 8;
                pfh[q] = *(const uint4*)&g_seqhi[so];
                pfl[q] = *(const uint4*)&g_seqlo[so];
            }
        } else {
#pragma unroll
            for (int q = 0; q < 8; q++) {
                const int v = tid + 256 * q;
                const int b = v >> 5, c = v & 31;
                pfh[q] = *(const uint4*)&g_hbhi[cur][(b0 + b) * H_ + c * 8];
                pfl[q] = *(const uint4*)&g_hblo[cur][(b0 + b) * H_ + c * 8];
            }
        }

        // ---- phase A: stage A-input as reg-batches (load-all -> STS-all) ----
        if (layer == 0) {
            uint4 ra[8];
#pragma unroll
            for (int q = 0; q < 4; q++) {
                const int v = tid + 256 * q;
                const int b = v >> 4, c = v & 15;
                const size_t so = ((size_t)(b0 + b) * T_ + t) * D_ + c * 8;
                ra[q * 2 + 0] = *(const uint4*)&g_xhi[so];
                ra[q * 2 + 1] = *(const uint4*)&g_xlo[so];
            }
#pragma unroll
            for (int q = 0; q < 4; q++) {
                const int v = tid + 256 * q;
                const int b = v >> 4, c = v & 15;
                *(uint4*)(sthi + b * 528 + c * 16) = ra[q * 2 + 0];
                *(uint4*)(stlo + b * 528 + c * 16) = ra[q * 2 + 1];
            }
        } else {
#pragma unroll
            for (int h2b = 0; h2b < 2; h2b++) {
                uint4 ra[8];
#pragma unroll
                for (int q = 0; q < 4; q++) {
                    const int v = tid + 256 * (h2b * 4 + q);
                    const int b = v >> 5, c = v & 31;
                    const size_t so = ((size_t)t * B_ + b0 + b) * H_ + c * 8;
                    ra[q * 2 + 0] = *(const uint4*)&g_seqhi[so];
                    ra[q * 2 + 1] = *(const uint4*)&g_seqlo[so];
                }
#pragma unroll
                for (int q = 0; q < 4; q++) {
                    const int v = tid + 256 * (h2b * 4 + q);
                    const int b = v >> 5, c = v & 31;
                    *(uint4*)(sthi + b * 528 + c * 16) = ra[q * 2 + 0];
                    *(uint4*)(stlo + b * 528 + c * 16) = ra[q * 2 + 1];
                }
            }
        }
        __syncthreads();

        float acc[6][4], accN[2][4];
#pragma unroll
        for (int nt = 0; nt < 6; nt++)
#pragma unroll
            for (int q = 0; q < 4; q++) acc[nt][q] = 0.f;
#pragma unroll
        for (int nt = 0; nt < 2; nt++)
#pragma unroll
            for (int q = 0; q < 4; q++) accN[nt][q] = 0.f;

        const int kbaseA = kh * KA;          // byte offset of this warp's K-half
#pragma unroll 4
        for (int ks = 0; ks < nksA; ks++) {
            const int kb = kbaseA + ks * 32;
            uint32_t ah[4], al[4], bh[6][2], bl[6][2];
            LDSM4(ah[0], ah[1], ah[2], ah[3], uSth + aoff + kb);
            LDSM4(al[0], al[1], al[2], al[3], uStl + aoff + kb);
#pragma unroll
            for (int p = 0; p < 3; p++) {
                const uint32_t rb = (uint32_t)((p * 16 + brow) * 528 + bko + kb);
                uint32_t t0, t1, t2, t3;
                LDSM4(t0, t1, t2, t3, uIhi + rb);
                bh[p * 2][0] = t0; bh[p * 2][1] = t1;
                bh[p * 2 + 1][0] = t2; bh[p * 2 + 1][1] = t3;
                LDSM4(t0, t1, t2, t3, uIlo + rb);
                bl[p * 2][0] = t0; bl[p * 2][1] = t1;
                bl[p * 2 + 1][0] = t2; bl[p * 2 + 1][1] = t3;
            }
#pragma unroll
            for (int nt = 0; nt < 6; nt++) {
                MMA16816(acc[nt], ah, bh[nt][0], bh[nt][1]);
                MMA16816(acc[nt], ah, bl[nt][0], bl[nt][1]);
                MMA16816(acc[nt], al, bh[nt][0], bh[nt][1]);
            }
        }
        __syncthreads();   // phase-A reads of stage buffer complete

        // ---- phase B: store prefetched h_prev (STS only), GEMM vs Whh slice ----
#pragma unroll
        for (int q = 0; q < 8; q++) {
            const int v = tid + 256 * q;
            const int b = v >> 5, c = v & 31;
            *(uint4*)(sthi + b * 528 + c * 16) = pfh[q];
            *(uint4*)(stlo + b * 528 + c * 16) = pfl[q];
        }
        __syncthreads();

#pragma unroll
        for (int ks = 0; ks < 8; ks++) {
            const int kb = kh * 256 + ks * 32;
            uint32_t ah[4], al[4], bh[6][2], bl[6][2];
            LDSM4(ah[0], ah[1], ah[2], ah[3], uSth + aoff + kb);
            LDSM4(al[0], al[1], al[2], al[3], uStl + aoff + kb);
#pragma unroll
            for (int p = 0; p < 3; p++) {
                const uint32_t rb = (uint32_t)((p * 16 + brow) * 528 + bko + kb);
                uint32_t t0, t1, t2, t3;
                LDSM4(t0, t1, t2, t3, uHhi + rb);
                bh[p * 2][0] = t0; bh[p * 2][1] = t1;
                bh[p * 2 + 1][0] = t2; bh[p * 2 + 1][1] = t3;
                LDSM4(t0, t1, t2, t3, uHlo + rb);
                bl[p * 2][0] = t0; bl[p * 2][1] = t1;
                bl[p * 2 + 1][0] = t2; bl[p * 2 + 1][1] = t3;
            }
#pragma unroll
            for (int nt = 0; nt < 4; nt++) {
                MMA16816(acc[nt], ah, bh[nt][0], bh[nt][1]);
                MMA16816(acc[nt], ah, bl[nt][0], bl[nt][1]);
                MMA16816(acc[nt], al, bh[nt][0], bh[nt][1]);
            }
#pragma unroll
            for (int nt = 4; nt < 6; nt++) {
                MMA16816(accN[nt - 4], ah, bh[nt][0], bh[nt][1]);
                MMA16816(accN[nt - 4], ah, bl[nt][0], bl[nt][1]);
                MMA16816(accN[nt - 4], al, bh[nt][0], bh[nt][1]);
            }
        }
        {
            const int prow = mt * 16 + (lane >> 2);
            float* pp = &part[(kh * 64 + prow) * 49];
            float* p8 = pp + 8 * 49;
            const int c2 = 2 * (lane & 3);
#pragma unroll
            for (int nt = 0; nt < 6; nt++) {
                pp[nt * 8 + c2] = acc[nt][0]; pp[nt * 8 + c2 + 1] = acc[nt][1];
                p8[nt * 8 + c2] = acc[nt][2]; p8[nt * 8 + c2 + 1] = acc[nt][3];
            }
            float* pn = &partN[kh * 1088 + prow * 17];
            float* pn8 = pn + 8 * 17;
#pragma unroll
            for (int nt = 0; nt < 2; nt++) {
                pn[nt * 8 + c2] = accN[nt][0]; pn[nt * 8 + c2 + 1] = accN[nt][1];
                pn8[nt * 8 + c2] = accN[nt][2]; pn8[nt * 8 + c2 + 1] = accN[nt][3];
            }
        }
        __syncthreads();

        // ---- gates: 4 (b,jj) per thread, in-place hst update (exclusive owner) ----
#pragma unroll
        for (int p = 0; p < 4; p++) {
            const int pr = tid + p * 256;
            const int b = pr & 63, jj = pr >> 6;
            const float* p0 = &part[b * 49];
            const float* p1 = &part[(64 + b) * 49];
            const float sr = bih[jj] + bhh[jj] + p0[jj] + p1[jj];
            const float sz = bih[16 + jj] + bhh[16 + jj] + p0[16 + jj] + p1[16 + jj];
            const float gin = bih[32 + jj] + p0[32 + jj] + p1[32 + jj];
            const float ghn = bhh[32 + jj]
                            + partN[b * 17 + jj] + partN[1088 + b * 17 + jj];
            const float r = __fdividef(1.f, 1.f + __expf(-sr));
            const float z = __fdividef(1.f, 1.f + __expf(-sz));
            const float a = gin + r * ghn;
            const float n = __fdividef(2.f, 1.f + __expf(-2.f * a)) - 1.f;
            hst[b * 17 + jj] = (1.f - z) * n + z * hst[b * 17 + jj];
        }
        __syncthreads();

        // ---- publish h(t) ----
        if (tid < 128) {
            const int b = tid >> 1, seg = tid & 1;
            float f[8];
            union { __nv_bfloat16 a8[8]; uint4 u; } uhi, ulo;
#pragma unroll
            for (int j = 0; j < 8; j++) {
                f[j] = hst[b * 17 + seg * 8 + j];
                uhi.a8[j] = __float2bfloat16(f[j]);
                ulo.a8[j] = __float2bfloat16(f[j] - __bfloat162float(uhi.a8[j]));
            }
            if (layer == 0) {
                const size_t so = ((size_t)t * B_ + b0 + b) * H_ + j0 + seg * 8;
                *(uint4*)&g_seqhi[so] = uhi.u;
                *(uint4*)&g_seqlo[so] = ulo.u;
            } else {
                const size_t go = (size_t)(b0 + b) * H_ + j0 + seg * 8;
                *(uint4*)&g_hbhi[nxt][go] = uhi.u;
                *(uint4*)&g_hblo[nxt][go] = ulo.u;
                if (t == T_ - 1) {
                    *(float4*)&g_hlast[go]     = make_float4(f[0], f[1], f[2], f[3]);
                    *(float4*)&g_hlast[go + 4] = make_float4(f[4], f[5], f[6], f[7]);
                }
            }
        }

        // ---- per-layer 16-CTA group barrier ----
        __threadfence();
        __syncthreads();
        if (tid == 0) {
            const unsigned a = atomicAdd(&cntp[slot], 1u);
            if (a == 15u) {
                cntp[slot] = 0u;
                __threadfence();
                genp[slot] = (unsigned)(t + 1);
            } else {
                while (genp[slot] < (unsigned)(t + 1)) {}
            }
            __threadfence();
        }
        __syncthreads();
    }
}

// ---------------- final FC: out[256,10] = h @ Wfc^T + bfc -------------------------
// all Wfc loads hoisted into one MLP batch; 10 independent shuffle-reduce chains
__global__ void fc_kernel(const float* __restrict__ h, const float* __restrict__ Wfc,
                          const float* __restrict__ bfc, float* __restrict__ out)
{
    const int b = blockIdx.x;
    const int lane = threadIdx.x;
    float hv[8];
#pragma unroll
    for (int i = 0; i < 8; i++) hv[i] = h[b * H_ + lane + 32 * i];
    float wf[10][8];
#pragma unroll
    for (int cc = 0; cc < C_; cc++)
#pragma unroll
        for (int i = 0; i < 8; i++) wf[cc][i] = Wfc[cc * H_ + lane + 32 * i];
    float s[10];
#pragma unroll
    for (int cc = 0; cc < C_; cc++) {
        float t = 0.f;
#pragma unroll
        for (int i = 0; i < 8; i++) t += hv[i] * wf[cc][i];
        s[cc] = t;
    }
#pragma unroll
    for (int o = 16; o > 0; o >>= 1)
#pragma unroll
        for (int cc = 0; cc < C_; cc++)
            s[cc] += __shfl_down_sync(0xffffffffu, s[cc], o);
    if (lane == 0) {
#pragma unroll
        for (int cc = 0; cc < C_; cc++)
            out[b * C_ + cc] = s[cc] + bfc[cc];
    }
}

// ---------------- launch ----------------------------------------------------------
extern "C" void kernel_launch(void* const* d_in, const int* in_sizes, int n_in,
                              void* d_out, int out_size)
{
    (void)in_sizes; (void)n_in; (void)out_size;
    const float* x    = (const float*)d_in[0];
    const float* Wih0 = (const float*)d_in[1];
    const float* Whh0 = (const float*)d_in[2];
    const float* bih0 = (const float*)d_in[3];
    const float* bhh0 = (const float*)d_in[4];
    const float* Wih1 = (const float*)d_in[5];
    const float* Whh1 = (const float*)d_in[6];
    const float* bih1 = (const float*)d_in[7];
    const float* bhh1 = (const float*)d_in[8];
    const float* Wfc  = (const float*)d_in[9];
    const float* bfc  = (const float*)d_in[10];
    float* out = (float*)d_out;

    float* p_hl;
    __nv_bfloat16 *p_xhi, *p_xlo;
    cudaGetSymbolAddress((void**)&p_hl, g_hlast);
    cudaGetSymbolAddress((void**)&p_xhi, g_xhi);
    cudaGetSymbolAddress((void**)&p_xlo, g_xlo);

    const int fused_smem = 207488;
    cudaFuncSetAttribute(gru_fused2, cudaFuncAttributeMaxDynamicSharedMemorySize, fused_smem);

    // split x (bf16 hi/lo) + reset barrier state (fused); then the fused scan
    split_bf16<<<(B_ * T_ * D_ / 4 + 255) / 256, 256>>>(x, p_xhi, p_xlo, B_ * T_ * D_ / 4);

    gru_fused2<<<128, 256, fused_smem>>>(Wih0, bih0, Whh0, bhh0,
                                         Wih1, bih1, Whh1, bhh1);

    // classifier on final hidden state
    fc_kernel<<<B_, 32>>>(p_hl, Wfc, bfc, out);
}

// round 17
// speedup vs baseline: 1.0682x; 1.0682x over previous
#include <cuda_runtime.h>
#include <cuda_fp16.h>
#include <math.h>
#include <stdint.h>

#define B_  256
#define T_  512
#define D_  128
#define H_  256
#define G_  768
#define C_  10

// ---------------- warp-mma helpers (sm_80+ baseline; compiles for plain sm_103) ---
__device__ __forceinline__ uint32_t smem_u32(const void* p) {
    uint32_t a;
    asm("{ .reg .u64 t; cvta.to.shared.u64 t, %1; cvt.u32.u64 %0, t; }" : "=r"(a) : "l"(p));
    return a;
}
#define LDSM4(r0, r1, r2, r3, addr) \
    asm volatile("ldmatrix.sync.aligned.m8n8.x4.shared.b16 {%0,%1,%2,%3}, [%4];" \
        : "=r"(r0), "=r"(r1), "=r"(r2), "=r"(r3) : "r"(addr))
#define MMA16816(c, a, b0v, b1v) \
    asm volatile("mma.sync.aligned.m16n8k16.row.col.f32.f16.f16.f32 " \
        "{%0,%1,%2,%3},{%4,%5,%6,%7},{%8,%9},{%0,%1,%2,%3};" \
        : "+f"((c)[0]), "+f"((c)[1]), "+f"((c)[2]), "+f"((c)[3]) \
        : "r"((a)[0]), "r"((a)[1]), "r"((a)[2]), "r"((a)[3]), "r"(b0v), "r"(b1v))

// ---------------- scratch (device globals; no allocation allowed) ----------------
__device__ __half g_seq[(size_t)T_ * B_ * H_];   // layer-0 h sequence (fp16)
__device__ __half g_hb[2][B_ * H_];              // layer-1 h ping-pong (fp16)
__device__ float g_hlast[B_ * H_];               // final fp32 h2 for the FC
__device__ volatile unsigned g_gen0[4 * 32];     // layer-0 group generation
__device__ unsigned g_cnt0[4 * 32];
__device__ volatile unsigned g_gen1[4 * 32];     // layer-1 group generation
__device__ unsigned g_cnt1[4 * 32];
__device__ __half g_x16[(size_t)B_ * T_ * D_];   // x as fp16

// ---------------- fp32 -> fp16 convert + barrier reset (fused) ---------------------
__global__ void conv_x(const float* __restrict__ s, __half* __restrict__ d, int n4)
{
    if (blockIdx.x == 0 && threadIdx.x < 128) {
        const int i = threadIdx.x;
        g_cnt0[i] = 0u; ((unsigned*)g_gen0)[i] = 0u;
        g_cnt1[i] = 0u; ((unsigned*)g_gen1)[i] = 0u;
    }
    const int i = blockIdx.x * blockDim.x + threadIdx.x;
    if (i >= n4) return;
    const float4 v = ((const float4*)s)[i];
    __half2* dp = (__half2*)d;
    dp[i * 2 + 0] = __floats2half2_rn(v.x, v.y);
    dp[i * 2 + 1] = __floats2half2_rn(v.z, v.w);
}

// ---------------- fully fused two-layer GRU, 2-pass fp16 ---------------------------
// 128 CTAs x 256 threads. CTA<64: layer 0; CTA>=64: layer 1 (lags one step).
// Activations fp16 (no residual); weights split fp16 hi+lo in smem.
// Per phase per k-step: 1 LDSM4 (A) + 6 LDSM4 (W hi/lo) + 12 MMA (6 tiles x 2 pass).
// smem: sih_h 0, sih_l 25344, shh_h 50688, shh_l 76032 (each 48x264 fp16);
//       stage 101376 (64x528B); part 135168 (2x64x49 f32); partN 160256 (2x64x17);
//       hst 168960 (64x17 f32); bih 173312; bhh 173504. total 173696.
__global__ void __launch_bounds__(256, 1) gru_fused2(
    const float* __restrict__ Wih0, const float* __restrict__ bih0,
    const float* __restrict__ Whh0, const float* __restrict__ bhh0,
    const float* __restrict__ Wih1, const float* __restrict__ bih1,
    const float* __restrict__ Whh1, const float* __restrict__ bhh1)
{
    extern __shared__ char smc[];
    __half* sih_h = (__half*)smc;
    __half* sih_l = (__half*)(smc + 25344);
    __half* shh_h = (__half*)(smc + 50688);
    __half* shh_l = (__half*)(smc + 76032);
    char* stg = smc + 101376;
    float* part  = (float*)(smc + 135168);
    float* partN = (float*)(smc + 160256);
    float* hst   = (float*)(smc + 168960);
    float* bih   = (float*)(smc + 173312);
    float* bhh   = (float*)(smc + 173504);

    const int tid = threadIdx.x;
    const int cta = blockIdx.x;
    const int layer = cta >> 6;
    const int lid = cta & 63;
    const int bblk = lid >> 4, jblk = lid & 15;
    const int b0 = bblk * 64, j0 = jblk * 16;
    const int slot = bblk * 32;

    const float* WA = layer ? Wih1 : Wih0;
    const float* WB = layer ? Whh1 : Whh0;
    const float* bA = layer ? bih1 : bih0;
    const float* bB = layer ? bhh1 : bhh0;
    const int KA = layer ? 256 : 128;          // phase-A K
    const int nksA = layer ? 8 : 4;
    volatile unsigned* genp = layer ? g_gen1 : g_gen0;
    unsigned* cntp = layer ? g_cnt1 : g_cnt0;

    // ---- load + split weight slices into fp16 hi/lo (48 gate rows each) ----
    for (int idx = tid; idx < 48 * KA; idx += 256) {
        const int row = idx / KA, k = idx % KA;
        const float v = WA[(size_t)((row >> 4) * H_ + j0 + (row & 15)) * KA + k];
        const __half hi = __float2half(v);
        sih_h[row * 264 + k] = hi;
        sih_l[row * 264 + k] = __float2half(v - __half2float(hi));
    }
    for (int idx = tid; idx < 48 * 256; idx += 256) {
        const int row = idx >> 8, k = idx & 255;
        const float v = WB[(size_t)((row >> 4) * H_ + j0 + (row & 15)) * H_ + k];
        const __half hi = __float2half(v);
        shh_h[row * 264 + k] = hi;
        shh_l[row * 264 + k] = __float2half(v - __half2float(hi));
    }
    if (tid < 48) {
        bih[tid] = bA[(tid >> 4) * H_ + j0 + (tid & 15)];
        bhh[tid] = bB[(tid >> 4) * H_ + j0 + (tid & 15)];
    }
    for (int idx = tid; idx < 64 * 17; idx += 256) hst[idx] = 0.f;

    const int w = tid >> 5, lane = tid & 31;
    const int mt = w & 3, kh = w >> 2;
    const int aoff = (mt * 16 + (lane & 15)) * 528 + (lane >> 4) * 16;
    const int brow = (lane & 7) + ((lane >> 4) << 3);
    const int bko  = ((lane >> 3) & 1) * 16;
    const uint32_t uStg = smem_u32(stg);
    const uint32_t uIhi = smem_u32(smc), uIlo = smem_u32(smc + 25344);
    const uint32_t uHhi = smem_u32(smc + 50688), uHlo = smem_u32(smc + 76032);
    __syncthreads();

    for (int t = 0; t < T_; t++) {
        const int cur = t & 1, nxt = cur ^ 1;

        // layer-1 waits for layer-0 to have produced h1(t)
        if (layer == 1) {
            if (tid == 0) {
                while (g_gen0[slot] < (unsigned)(t + 1)) {}
                __threadfence();
            }
            __syncthreads();
        }

        // ---- prefetch phase-B staging into registers (covered by phase A) ----
        uint4 pfh[8];
        if (t == 0) {
            const uint4 z4 = make_uint4(0u, 0u, 0u, 0u);
#pragma unroll
            for (int q = 0; q < 8; q++) pfh[q] = z4;
        } else if (layer == 0) {
#pragma unroll
            for (int q = 0; q < 8; q++) {
                const int v = tid + 256 * q;
                const int b = v >> 5, c = v & 31;
                pfh[q] = *(const uint4*)&g_seq[((size_t)(t - 1) * B_ + b0 + b) * H_ + c * 8];
            }
        } else {
#pragma unroll
            for (int q = 0; q < 8; q++) {
                const int v = tid + 256 * q;
                const int b = v >> 5, c = v & 31;
                pfh[q] = *(const uint4*)&g_hb[cur][(b0 + b) * H_ + c * 8];
            }
        }

        // ---- phase A: stage A-input (fp16), GEMM vs Wih hi/lo ----
        if (layer == 0) {
#pragma unroll
            for (int q = 0; q < 4; q++) {
                const int v = tid + 256 * q;
                const int b = v >> 4, c = v & 15;
                *(uint4*)(stg + b * 528 + c * 16) =
                    *(const uint4*)&g_x16[((size_t)(b0 + b) * T_ + t) * D_ + c * 8];
            }
        } else {
#pragma unroll
            for (int q = 0; q < 8; q++) {
                const int v = tid + 256 * q;
                const int b = v >> 5, c = v & 31;
                *(uint4*)(stg + b * 528 + c * 16) =
                    *(const uint4*)&g_seq[((size_t)t * B_ + b0 + b) * H_ + c * 8];
            }
        }
        __syncthreads();

        float acc[6][4], accN[2][4];
#pragma unroll
        for (int nt = 0; nt < 6; nt++)
#pragma unroll
            for (int q = 0; q < 4; q++) acc[nt][q] = 0.f;
#pragma unroll
        for (int nt = 0; nt < 2; nt++)
#pragma unroll
            for (int q = 0; q < 4; q++) accN[nt][q] = 0.f;

        const int kbaseA = kh * KA;          // byte offset of this warp's K-half
#pragma unroll 4
        for (int ks = 0; ks < nksA; ks++) {
            const int kb = kbaseA + ks * 32;
            uint32_t ah[4], bh[6][2], bl[6][2];
            LDSM4(ah[0], ah[1], ah[2], ah[3], uStg + aoff + kb);
#pragma unroll
            for (int p = 0; p < 3; p++) {
                const uint32_t rb = (uint32_t)((p * 16 + brow) * 528 + bko + kb);
                uint32_t t0, t1, t2, t3;
                LDSM4(t0, t1, t2, t3, uIhi + rb);
                bh[p * 2][0] = t0; bh[p * 2][1] = t1;
                bh[p * 2 + 1][0] = t2; bh[p * 2 + 1][1] = t3;
                LDSM4(t0, t1, t2, t3, uIlo + rb);
                bl[p * 2][0] = t0; bl[p * 2][1] = t1;
                bl[p * 2 + 1][0] = t2; bl[p * 2 + 1][1] = t3;
            }
#pragma unroll
            for (int nt = 0; nt < 6; nt++) {
                MMA16816(acc[nt], ah, bh[nt][0], bh[nt][1]);
                MMA16816(acc[nt], ah, bl[nt][0], bl[nt][1]);
            }
        }
        __syncthreads();   // phase-A reads of stage buffer complete

        // ---- phase B: store prefetched h_prev (STS only), GEMM vs Whh hi/lo ----
#pragma unroll
        for (int q = 0; q < 8; q++) {
            const int v = tid + 256 * q;
            const int b = v >> 5, c = v & 31;
            *(uint4*)(stg + b * 528 + c * 16) = pfh[q];
        }
        __syncthreads();

#pragma unroll
        for (int ks = 0; ks < 8; ks++) {
            const int kb = kh * 256 + ks * 32;
            uint32_t ah[4], bh[6][2], bl[6][2];
            LDSM4(ah[0], ah[1], ah[2], ah[3], uStg + aoff + kb);
#pragma unroll
            for (int p = 0; p < 3; p++) {
                const uint32_t rb = (uint32_t)((p * 16 + brow) * 528 + bko + kb);
                uint32_t t0, t1, t2, t3;
                LDSM4(t0, t1, t2, t3, uHhi + rb);
                bh[p * 2][0] = t0; bh[p * 2][1] = t1;
                bh[p * 2 + 1][0] = t2; bh[p * 2 + 1][1] = t3;
                LDSM4(t0, t1, t2, t3, uHlo + rb);
                bl[p * 2][0] = t0; bl[p * 2][1] = t1;
                bl[p * 2 + 1][0] = t2; bl[p * 2 + 1][1] = t3;
            }
#pragma unroll
            for (int nt = 0; nt < 4; nt++) {
                MMA16816(acc[nt], ah, bh[nt][0], bh[nt][1]);
                MMA16816(acc[nt], ah, bl[nt][0], bl[nt][1]);
            }
#pragma unroll
            for (int nt = 4; nt < 6; nt++) {
                MMA16816(accN[nt - 4], ah, bh[nt][0], bh[nt][1]);
                MMA16816(accN[nt - 4], ah, bl[nt][0], bl[nt][1]);
            }
        }
        {
            const int prow = mt * 16 + (lane >> 2);
            float* pp = &part[(kh * 64 + prow) * 49];
            float* p8 = pp + 8 * 49;
            const int c2 = 2 * (lane & 3);
#pragma unroll
            for (int nt = 0; nt < 6; nt++) {
                pp[nt * 8 + c2] = acc[nt][0]; pp[nt * 8 + c2 + 1] = acc[nt][1];
                p8[nt * 8 + c2] = acc[nt][2]; p8[nt * 8 + c2 + 1] = acc[nt][3];
            }
            float* pn = &partN[kh * 1088 + prow * 17];
            float* pn8 = pn + 8 * 17;
#pragma unroll
            for (int nt = 0; nt < 2; nt++) {
                pn[nt * 8 + c2] = accN[nt][0]; pn[nt * 8 + c2 + 1] = accN[nt][1];
                pn8[nt * 8 + c2] = accN[nt][2]; pn8[nt * 8 + c2 + 1] = accN[nt][3];
            }
        }
        __syncthreads();

        // ---- gates: 4 (b,jj) per thread, in-place hst update (exclusive owner) ----
#pragma unroll
        for (int p = 0; p < 4; p++) {
            const int pr = tid + p * 256;
            const int b = pr & 63, jj = pr >> 6;
            const float* p0 = &part[b * 49];
            const float* p1 = &part[(64 + b) * 49];
            const float sr = bih[jj] + bhh[jj] + p0[jj] + p1[jj];
            const float sz = bih[16 + jj] + bhh[16 + jj] + p0[16 + jj] + p1[16 + jj];
            const float gin = bih[32 + jj] + p0[32 + jj] + p1[32 + jj];
            const float ghn = bhh[32 + jj]
                            + partN[b * 17 + jj] + partN[1088 + b * 17 + jj];
            const float r = __fdividef(1.f, 1.f + __expf(-sr));
            const float z = __fdividef(1.f, 1.f + __expf(-sz));
            const float a = gin + r * ghn;
            const float n = __fdividef(2.f, 1.f + __expf(-2.f * a)) - 1.f;
            hst[b * 17 + jj] = (1.f - z) * n + z * hst[b * 17 + jj];
        }
        __syncthreads();

        // ---- publish h(t) as fp16 ----
        if (tid < 128) {
            const int b = tid >> 1, seg = tid & 1;
            float f[8];
            union { __half a8[8]; uint4 u; } uh;
#pragma unroll
            for (int j = 0; j < 8; j++) {
                f[j] = hst[b * 17 + seg * 8 + j];
                uh.a8[j] = __float2half(f[j]);
            }
            if (layer == 0) {
                *(uint4*)&g_seq[((size_t)t * B_ + b0 + b) * H_ + j0 + seg * 8] = uh.u;
            } else {
                const size_t go = (size_t)(b0 + b) * H_ + j0 + seg * 8;
                *(uint4*)&g_hb[nxt][go] = uh.u;
                if (t == T_ - 1) {
                    *(float4*)&g_hlast[go]     = make_float4(f[0], f[1], f[2], f[3]);
                    *(float4*)&g_hlast[go + 4] = make_float4(f[4], f[5], f[6], f[7]);
                }
            }
        }

        // ---- per-layer 16-CTA group barrier ----
        __threadfence();
        __syncthreads();
        if (tid == 0) {
            const unsigned a = atomicAdd(&cntp[slot], 1u);
            if (a == 15u) {
                cntp[slot] = 0u;
                __threadfence();
                genp[slot] = (unsigned)(t + 1);
            } else {
                while (genp[slot] < (unsigned)(t + 1)) {}
            }
            __threadfence();
        }
        __syncthreads();
    }
}

// ---------------- final FC: out[256,10] = h @ Wfc^T + bfc -------------------------
__global__ void fc_kernel(const float* __restrict__ h, const float* __restrict__ Wfc,
                          const float* __restrict__ bfc, float* __restrict__ out)
{
    const int b = blockIdx.x;
    const int lane = threadIdx.x;
    float hv[8];
#pragma unroll
    for (int i = 0; i < 8; i++) hv[i] = h[b * H_ + lane + 32 * i];
    float wf[10][8];
#pragma unroll
    for (int cc = 0; cc < C_; cc++)
#pragma unroll
        for (int i = 0; i < 8; i++) wf[cc][i] = Wfc[cc * H_ + lane + 32 * i];
    float s[10];
#pragma unroll
    for (int cc = 0; cc < C_; cc++) {
        float t = 0.f;
#pragma unroll
        for (int i = 0; i < 8; i++) t += hv[i] * wf[cc][i];
        s[cc] = t;
    }
#pragma unroll
    for (int o = 16; o > 0; o >>= 1)
#pragma unroll
        for (int cc = 0; cc < C_; cc++)
            s[cc] += __shfl_down_sync(0xffffffffu, s[cc], o);
    if (lane == 0) {
#pragma unroll
        for (int cc = 0; cc < C_; cc++)
            out[b * C_ + cc] = s[cc] + bfc[cc];
    }
}

// ---------------- launch ----------------------------------------------------------
extern "C" void kernel_launch(void* const* d_in, const int* in_sizes, int n_in,
                              void* d_out, int out_size)
{
    (void)in_sizes; (void)n_in; (void)out_size;
    const float* x    = (const float*)d_in[0];
    const float* Wih0 = (const float*)d_in[1];
    const float* Whh0 = (const float*)d_in[2];
    const float* bih0 = (const float*)d_in[3];
    const float* bhh0 = (const float*)d_in[4];
    const float* Wih1 = (const float*)d_in[5];
    const float* Whh1 = (const float*)d_in[6];
    const float* bih1 = (const float*)d_in[7];
    const float* bhh1 = (const float*)d_in[8];
    const float* Wfc  = (const float*)d_in[9];
    const float* bfc  = (const float*)d_in[10];
    float* out = (float*)d_out;

    float* p_hl;
    __half* p_x16;
    cudaGetSymbolAddress((void**)&p_hl, g_hlast);
    cudaGetSymbolAddress((void**)&p_x16, g_x16);

    const int fused_smem = 173696;
    cudaFuncSetAttribute(gru_fused2, cudaFuncAttributeMaxDynamicSharedMemorySize, fused_smem);

    // convert x to fp16 + reset barrier state (fused); then the fused scan
    conv_x<<<(B_ * T_ * D_ / 4 + 255) / 256, 256>>>(x, p_x16, B_ * T_ * D_ / 4);

    gru_fused2<<<128, 256, fused_smem>>>(Wih0, bih0, Whh0, bhh0,
                                         Wih1, bih1, Whh1, bhh1);

    // classifier on final hidden state
    fc_kernel<<<B_, 32>>>(p_hl, Wfc, bfc, out);
}